// round 10
// baseline (speedup 1.0000x reference)
#include <cuda_runtime.h>

// Problem constants (fixed by setup_inputs)
#define BB 16
#define HH 2048
#define WW 2048
#define SS 5000
#define NST (BB * SS)          // 80000 stations

#define THREADS 256
#define NBLK 304                           // 2 CTAs/SM x 152 SMs -> ONE wave
#define TOTTH (NBLK * THREADS)             // 77824 threads
#define LEFTOVER (NST - TOTTH)             // 2176 threads carry a 2nd station

#define INV_NST (1.0f / (float)NST)

// Volatile PTX loads: volatile asms keep source order, so all loads issued
// through these helpers are batched back-to-back (max MLP) and cannot be
// sunk to their consumption points by ptxas.
__device__ __forceinline__ float2 ldg_f2(const float* p)
{
    float2 v;
    asm volatile("ld.global.nc.v2.f32 {%0,%1}, [%2];"
                 : "=f"(v.x), "=f"(v.y) : "l"(p));
    return v;
}
__device__ __forceinline__ int2 ldg_i2(const int* p)
{
    int2 v;
    asm volatile("ld.global.nc.v2.s32 {%0,%1}, [%2];"
                 : "=r"(v.x), "=r"(v.y) : "l"(p));
    return v;
}
__device__ __forceinline__ float ldg_f1(const float* p)
{
    float v;
    asm volatile("ld.global.nc.f32 %0, [%1];" : "=f"(v) : "l"(p));
    return v;
}

// Select element r (0..3) from the 4-float window {a.x, a.y, b.x, b.y}.
__device__ __forceinline__ float sel4(float2 a, float2 b, int r)
{
    const float lo = (r & 1) ? a.y : a.x;
    const float hi = (r & 1) ? b.y : b.x;
    return (r & 2) ? hi : lo;
}

struct StAddr {
    const float* r0;
    const float* r1;
    const float* r2;
    int rA, rB, rC;
    float f0, f2, g0, g2;
};

__device__ __forceinline__ StAddr make_addr(const float* __restrict__ pred,
                                            int b, int x, int y)
{
    StAddr s;
    const float* p = pred + (long long)b * (HH * WW);

    int xa = max(x - 1, 0);
    xa = min(xa, WW - 4);
    xa &= ~1;

    const int ym1 = max(y - 1, 0);
    const int yp1 = min(y + 1, HH - 1);

    s.r0 = p + ym1 * WW + xa;
    s.r1 = p + y   * WW + xa;
    s.r2 = p + yp1 * WW + xa;

    const int xm1 = max(x - 1, 0);
    const int xp1 = min(x + 1, WW - 1);
    s.rA = xm1 - xa;
    s.rB = x   - xa;
    s.rC = xp1 - xa;

    s.f0 = (x - 1 >= 0) ? 1.0f : 0.0f;
    s.f2 = (x + 1 < WW) ? 1.0f : 0.0f;
    s.g0 = (y - 1 >= 0) ? 1.0f : 0.0f;
    s.g2 = (y + 1 < HH) ? 1.0f : 0.0f;
    return s;
}

__device__ __forceinline__ float window_loss(const StAddr& s,
                                             float2 a0, float2 b0,
                                             float2 a1, float2 b1,
                                             float2 a2, float2 b2,
                                             float ro)
{
    // 1/cnt as product of exact/near-exact reciprocals: no FP divide in the
    // dependency tail (error ~1e-7 << 1e-3 threshold).
    const float rcp_col = (s.f0 + s.f2 == 2.0f) ? (1.0f / 3.0f) : 0.5f;
    const float rcp_row = (s.g0 + s.g2 == 2.0f) ? (1.0f / 3.0f) : 0.5f;

    const float s0 = s.f0 * sel4(a0, b0, s.rA) + sel4(a0, b0, s.rB) + s.f2 * sel4(a0, b0, s.rC);
    const float s1 = s.f0 * sel4(a1, b1, s.rA) + sel4(a1, b1, s.rB) + s.f2 * sel4(a1, b1, s.rC);
    const float s2 = s.f0 * sel4(a2, b2, s.rA) + sel4(a2, b2, s.rB) + s.f2 * sel4(a2, b2, s.rC);
    const float sum  = s.g0 * s0 + s1 + s.g2 * s2;
    const float avg  = sum * rcp_col * rcp_row;
    const float diff = avg - ro;
    return diff * diff;
}

__global__ __launch_bounds__(THREADS, 2)
void station_loss_kernel(const float* __restrict__ pred,
                         const int*   __restrict__ pos,
                         const float* __restrict__ runoff,
                         float*       __restrict__ out)
{
    const int tid = blockIdx.x * blockDim.x + threadIdx.x;

    // Station 0 always valid (TOTTH <= NST); station 1 only for the first
    // LEFTOVER threads (predicated, clamped address -> safe duplicate).
    const int  sid0 = tid;
    const bool has1 = tid < LEFTOVER;
    const int  sid1 = has1 ? (tid + TOTTH) : tid;
    const float m1  = has1 ? 1.0f : 0.0f;

    // Phase 1: position loads (batched).
    const int2 p0 = ldg_i2(pos + 2 * sid0);
    const int2 p1 = ldg_i2(pos + 2 * sid1);

    // Phase 2: address generation.
    const StAddr A = make_addr(pred, sid0 / SS, p0.x, p0.y);
    const StAddr B = make_addr(pred, sid1 / SS, p1.x, p1.y);

    // Phase 3: all window loads + runoff loads, issued back-to-back.
    const float2 Aa0 = ldg_f2(A.r0);
    const float2 Ab0 = ldg_f2(A.r0 + 2);
    const float2 Aa1 = ldg_f2(A.r1);
    const float2 Ab1 = ldg_f2(A.r1 + 2);
    const float2 Aa2 = ldg_f2(A.r2);
    const float2 Ab2 = ldg_f2(A.r2 + 2);
    const float2 Ba0 = ldg_f2(B.r0);
    const float2 Bb0 = ldg_f2(B.r0 + 2);
    const float2 Ba1 = ldg_f2(B.r1);
    const float2 Bb1 = ldg_f2(B.r1 + 2);
    const float2 Ba2 = ldg_f2(B.r2);
    const float2 Bb2 = ldg_f2(B.r2 + 2);
    const float  ro0 = ldg_f1(runoff + sid0);
    const float  ro1 = ldg_f1(runoff + sid1);

    // Phase 4: arithmetic.
    const float acc = window_loss(A, Aa0, Ab0, Aa1, Ab1, Aa2, Ab2, ro0)
              + m1 * window_loss(B, Ba0, Bb0, Ba1, Bb1, Ba2, Bb2, ro1);

    // Deterministic block reduction: warp shuffle then shared-mem tree.
    __shared__ float smem[THREADS / 32];
    float v = acc;
    #pragma unroll
    for (int off = 16; off > 0; off >>= 1)
        v += __shfl_down_sync(0xFFFFFFFFu, v, off);
    const int lane = threadIdx.x & 31;
    const int warp = threadIdx.x >> 5;
    if (lane == 0) smem[warp] = v;
    __syncthreads();
    if (warp == 0) {
        v = (lane < THREADS / 32) ? smem[lane] : 0.0f;
        #pragma unroll
        for (int off = 16; off > 0; off >>= 1)
            v += __shfl_down_sync(0xFFFFFFFFu, v, off);
        // Fire-and-forget global reduction: one RED.ADD.F32 per block.
        if (lane == 0) atomicAdd(out, v * INV_NST);
    }
}

extern "C" void kernel_launch(void* const* d_in, const int* in_sizes, int n_in,
                              void* d_out, int out_size)
{
    const float* pred   = (const float*)d_in[0];  // (16,1,2048,2048) f32
    const int*   pos    = (const int*)  d_in[1];  // (16,5000,2) i32
    const float* runoff = (const float*)d_in[2];  // (16,5000) f32
    float* out = (float*)d_out;

    // Zero the 4-byte accumulator (graph-capturable async memset node).
    cudaMemsetAsync(out, 0, sizeof(float), 0);

    station_loss_kernel<<<NBLK, THREADS>>>(pred, pos, runoff, out);
}

// round 11
// speedup vs baseline: 1.1984x; 1.1984x over previous
#include <cuda_runtime.h>

// Problem constants (fixed by setup_inputs)
#define BB 16
#define HH 2048
#define WW 2048
#define SS 5000
#define NST (BB * SS)          // 80000 stations

#define THREADS 256
#define NBLK 304                           // 2 CTAs/SM x 152 SMs -> ONE wave
#define TOTTH (NBLK * THREADS)             // 77824 threads
#define LEFTOVER (NST - TOTTH)             // first 2176 threads take a 2nd station

#define INV_NST (1.0f / (float)NST)

// Volatile PTX loads: volatile asms keep source order, so all loads issued
// through these helpers are batched back-to-back (max MLP) and cannot be
// sunk to their consumption points by ptxas.
__device__ __forceinline__ float2 ldg_f2(const float* p)
{
    float2 v;
    asm volatile("ld.global.nc.v2.f32 {%0,%1}, [%2];"
                 : "=f"(v.x), "=f"(v.y) : "l"(p));
    return v;
}
__device__ __forceinline__ int2 ldg_i2(const int* p)
{
    int2 v;
    asm volatile("ld.global.nc.v2.s32 {%0,%1}, [%2];"
                 : "=r"(v.x), "=r"(v.y) : "l"(p));
    return v;
}
__device__ __forceinline__ float ldg_f1(const float* p)
{
    float v;
    asm volatile("ld.global.nc.f32 %0, [%1];" : "=f"(v) : "l"(p));
    return v;
}

// Select element r (0..3) from the 4-float window {a.x, a.y, b.x, b.y}.
__device__ __forceinline__ float sel4(float2 a, float2 b, int r)
{
    const float lo = (r & 1) ? a.y : a.x;
    const float hi = (r & 1) ? b.y : b.x;
    return (r & 2) ? hi : lo;
}

struct StAddr {
    const float* r0;
    const float* r1;
    const float* r2;
    int rA, rB, rC;
    float f0, f2, g0, g2;
};

__device__ __forceinline__ StAddr make_addr(const float* __restrict__ pred,
                                            int b, int x, int y)
{
    StAddr s;
    const float* p = pred + (long long)b * (HH * WW);

    int xa = max(x - 1, 0);
    xa = min(xa, WW - 4);
    xa &= ~1;

    const int ym1 = max(y - 1, 0);
    const int yp1 = min(y + 1, HH - 1);

    s.r0 = p + ym1 * WW + xa;
    s.r1 = p + y   * WW + xa;
    s.r2 = p + yp1 * WW + xa;

    const int xm1 = max(x - 1, 0);
    const int xp1 = min(x + 1, WW - 1);
    s.rA = xm1 - xa;
    s.rB = x   - xa;
    s.rC = xp1 - xa;

    s.f0 = (x - 1 >= 0) ? 1.0f : 0.0f;
    s.f2 = (x + 1 < WW) ? 1.0f : 0.0f;
    s.g0 = (y - 1 >= 0) ? 1.0f : 0.0f;
    s.g2 = (y + 1 < HH) ? 1.0f : 0.0f;
    return s;
}

__device__ __forceinline__ float window_loss(const StAddr& s,
                                             float2 a0, float2 b0,
                                             float2 a1, float2 b1,
                                             float2 a2, float2 b2,
                                             float ro)
{
    // 1/cnt as product of selected reciprocals: no FP divide in the tail
    // (error ~1e-7 << 1e-3 threshold).
    const float rcp_col = (s.f0 + s.f2 == 2.0f) ? (1.0f / 3.0f) : 0.5f;
    const float rcp_row = (s.g0 + s.g2 == 2.0f) ? (1.0f / 3.0f) : 0.5f;

    const float s0 = s.f0 * sel4(a0, b0, s.rA) + sel4(a0, b0, s.rB) + s.f2 * sel4(a0, b0, s.rC);
    const float s1 = s.f0 * sel4(a1, b1, s.rA) + sel4(a1, b1, s.rB) + s.f2 * sel4(a1, b1, s.rC);
    const float s2 = s.f0 * sel4(a2, b2, s.rA) + sel4(a2, b2, s.rB) + s.f2 * sel4(a2, b2, s.rC);
    const float sum  = s.g0 * s0 + s1 + s.g2 * s2;
    const float avg  = sum * rcp_col * rcp_row;
    const float diff = avg - ro;
    return diff * diff;
}

// Complete one-station gather + loss with forced-batch loads.
__device__ __forceinline__ float station_loss(const float* __restrict__ pred,
                                              const int*   __restrict__ pos,
                                              const float* __restrict__ runoff,
                                              int sid)
{
    const int2 pxy = ldg_i2(pos + 2 * sid);
    const StAddr A = make_addr(pred, sid / SS, pxy.x, pxy.y);
    const float2 a0 = ldg_f2(A.r0);
    const float2 b0 = ldg_f2(A.r0 + 2);
    const float2 a1 = ldg_f2(A.r1);
    const float2 b1 = ldg_f2(A.r1 + 2);
    const float2 a2 = ldg_f2(A.r2);
    const float2 b2 = ldg_f2(A.r2 + 2);
    const float  ro = ldg_f1(runoff + sid);
    return window_loss(A, a0, b0, a1, b1, a2, b2, ro);
}

__global__ __launch_bounds__(THREADS, 2)
void station_loss_kernel(const float* __restrict__ pred,
                         const int*   __restrict__ pos,
                         const float* __restrict__ runoff,
                         float*       __restrict__ out)
{
    const int tid = blockIdx.x * blockDim.x + threadIdx.x;

    // Every thread handles station tid (TOTTH <= NST). Only the first
    // LEFTOVER threads (whole warps in blocks 0..8) take a second station —
    // a real branch, so no wasted loads for the other 75648 threads.
    float acc = station_loss(pred, pos, runoff, tid);
    if (tid < LEFTOVER)
        acc += station_loss(pred, pos, runoff, tid + TOTTH);

    // Deterministic block reduction: warp shuffle then shared-mem tree.
    __shared__ float smem[THREADS / 32];
    float v = acc;
    #pragma unroll
    for (int off = 16; off > 0; off >>= 1)
        v += __shfl_down_sync(0xFFFFFFFFu, v, off);
    const int lane = threadIdx.x & 31;
    const int warp = threadIdx.x >> 5;
    if (lane == 0) smem[warp] = v;
    __syncthreads();
    if (warp == 0) {
        v = (lane < THREADS / 32) ? smem[lane] : 0.0f;
        #pragma unroll
        for (int off = 16; off > 0; off >>= 1)
            v += __shfl_down_sync(0xFFFFFFFFu, v, off);
        // Fire-and-forget global reduction: one RED.ADD.F32 per block.
        if (lane == 0) atomicAdd(out, v * INV_NST);
    }
}

extern "C" void kernel_launch(void* const* d_in, const int* in_sizes, int n_in,
                              void* d_out, int out_size)
{
    const float* pred   = (const float*)d_in[0];  // (16,1,2048,2048) f32
    const int*   pos    = (const int*)  d_in[1];  // (16,5000,2) i32
    const float* runoff = (const float*)d_in[2];  // (16,5000) f32
    float* out = (float*)d_out;

    // Zero the 4-byte accumulator (graph-capturable async memset node).
    cudaMemsetAsync(out, 0, sizeof(float), 0);

    station_loss_kernel<<<NBLK, THREADS>>>(pred, pos, runoff, out);
}

// round 12
// speedup vs baseline: 1.2520x; 1.0447x over previous
#include <cuda_runtime.h>

// Problem constants (fixed by setup_inputs)
#define BB 16
#define HH 2048
#define WW 2048
#define SS 5000
#define NST (BB * SS)          // 80000 stations

#define THREADS 256
#define NBLK 304                           // 2 CTAs/SM x 152 SMs -> ONE wave
#define TOTTH (NBLK * THREADS)             // 77824 threads
#define LEFTOVER (NST - TOTTH)             // first 2176 threads take a 2nd station

#define INV_NST (1.0f / (float)NST)

// Volatile PTX loads: volatile asms keep source order, so loads issued
// through these helpers are batched back-to-back (max MLP).
__device__ __forceinline__ float4 ldg_f4(const float* p)
{
    float4 v;
    asm volatile("ld.global.nc.v4.f32 {%0,%1,%2,%3}, [%4];"
                 : "=f"(v.x), "=f"(v.y), "=f"(v.z), "=f"(v.w) : "l"(p));
    return v;
}
__device__ __forceinline__ float2 ldg_f2(const float* p)
{
    float2 v;
    asm volatile("ld.global.nc.v2.f32 {%0,%1}, [%2];"
                 : "=f"(v.x), "=f"(v.y) : "l"(p));
    return v;
}
__device__ __forceinline__ int2 ldg_i2(const int* p)
{
    int2 v;
    asm volatile("ld.global.nc.v2.s32 {%0,%1}, [%2];"
                 : "=r"(v.x), "=r"(v.y) : "l"(p));
    return v;
}
__device__ __forceinline__ float ldg_f1(const float* p)
{
    float v;
    asm volatile("ld.global.nc.f32 %0, [%1];" : "=f"(v) : "l"(p));
    return v;
}

// Select element i (0..3) from a float4.
__device__ __forceinline__ float sel4q(float4 q, int i)
{
    const float lo = (i & 1) ? q.y : q.x;
    const float hi = (i & 1) ? q.w : q.z;
    return (i & 2) ? hi : lo;
}

// Row sum f0*v[xm1] + v[x] + f2*v[xp1] from the aligned float4 window q
// (covers xb..xb+3) and the spill float2 e (covers xe..xe+1, only read
// when an index exceeds 3).
__device__ __forceinline__ float row_sum(float4 q, float2 e,
                                         int i_m, int i_x, int i_p,
                                         int ex_x, int ex_p,
                                         float f0, float f2)
{
    const float vm = sel4q(q, i_m);                                   // i_m always 0..3
    const float vx = (i_x <= 3) ? sel4q(q, i_x) : (ex_x ? e.y : e.x);
    const float vp = (i_p <= 3) ? sel4q(q, i_p) : (ex_p ? e.y : e.x);
    return f0 * vm + vx + f2 * vp;
}

// Complete one-station gather + loss.
__device__ __forceinline__ float station_loss(const float* __restrict__ pred,
                                              const int*   __restrict__ pos,
                                              const float* __restrict__ runoff,
                                              int sid)
{
    const int2 pxy = ldg_i2(pos + 2 * sid);
    const int x = pxy.x;
    const int y = pxy.y;
    const float* __restrict__ p = pred + (long long)(sid / SS) * (HH * WW);

    // Column geometry (shared by all 3 rows).
    const int xm1 = max(x - 1, 0);
    const int xp1 = min(x + 1, WW - 1);
    const int xb  = xm1 & ~3;          // 16B-aligned, always in [0, WW-4]
    const int i_m = xm1 - xb;          // 0..3
    const int i_x = x   - xb;          // 0..4
    const int i_p = xp1 - xb;          // 0..5
    const bool need_e = (i_p > 3);     // implies spill float2 in bounds
    const int xe = min(xb + 4, WW - 2);
    const int ex_x = x   - xe;         // 0/1 when used
    const int ex_p = xp1 - xe;         // 0/1 when used

    const int ym1 = max(y - 1, 0);
    const int yp1 = min(y + 1, HH - 1);
    const float* r0 = p + ym1 * WW;
    const float* r1 = p + y   * WW;
    const float* r2 = p + yp1 * WW;

    // Batched gather: 3 x LDG.128 always; 3 x LDG.64 for ~50% of lanes.
    const float4 q0 = ldg_f4(r0 + xb);
    const float4 q1 = ldg_f4(r1 + xb);
    const float4 q2 = ldg_f4(r2 + xb);
    float2 e0 = make_float2(0.f, 0.f), e1 = e0, e2 = e0;
    if (need_e) {
        e0 = ldg_f2(r0 + xe);
        e1 = ldg_f2(r1 + xe);
        e2 = ldg_f2(r2 + xe);
    }
    const float ro = ldg_f1(runoff + sid);

    // Separable validity + reciprocal counts (no FP divide).
    const float f0 = (x - 1 >= 0) ? 1.0f : 0.0f;
    const float f2 = (x + 1 < WW) ? 1.0f : 0.0f;
    const float g0 = (y - 1 >= 0) ? 1.0f : 0.0f;
    const float g2 = (y + 1 < HH) ? 1.0f : 0.0f;
    const float rcp_col = (f0 + f2 == 2.0f) ? (1.0f / 3.0f) : 0.5f;
    const float rcp_row = (g0 + g2 == 2.0f) ? (1.0f / 3.0f) : 0.5f;

    const float s0 = row_sum(q0, e0, i_m, i_x, i_p, ex_x, ex_p, f0, f2);
    const float s1 = row_sum(q1, e1, i_m, i_x, i_p, ex_x, ex_p, f0, f2);
    const float s2 = row_sum(q2, e2, i_m, i_x, i_p, ex_x, ex_p, f0, f2);

    const float sum  = g0 * s0 + s1 + g2 * s2;
    const float avg  = sum * rcp_col * rcp_row;
    const float diff = avg - ro;
    return diff * diff;
}

__global__ __launch_bounds__(THREADS, 2)
void station_loss_kernel(const float* __restrict__ pred,
                         const int*   __restrict__ pos,
                         const float* __restrict__ runoff,
                         float*       __restrict__ out)
{
    const int tid = blockIdx.x * blockDim.x + threadIdx.x;

    // Every thread handles station tid (TOTTH <= NST). Only the first
    // LEFTOVER threads (whole warps in low blocks) take a second station.
    float acc = station_loss(pred, pos, runoff, tid);
    if (tid < LEFTOVER)
        acc += station_loss(pred, pos, runoff, tid + TOTTH);

    // Deterministic block reduction: warp shuffle then shared-mem tree.
    __shared__ float smem[THREADS / 32];
    float v = acc;
    #pragma unroll
    for (int off = 16; off > 0; off >>= 1)
        v += __shfl_down_sync(0xFFFFFFFFu, v, off);
    const int lane = threadIdx.x & 31;
    const int warp = threadIdx.x >> 5;
    if (lane == 0) smem[warp] = v;
    __syncthreads();
    if (warp == 0) {
        v = (lane < THREADS / 32) ? smem[lane] : 0.0f;
        #pragma unroll
        for (int off = 16; off > 0; off >>= 1)
            v += __shfl_down_sync(0xFFFFFFFFu, v, off);
        // Fire-and-forget global reduction: one RED.ADD.F32 per block.
        if (lane == 0) atomicAdd(out, v * INV_NST);
    }
}

extern "C" void kernel_launch(void* const* d_in, const int* in_sizes, int n_in,
                              void* d_out, int out_size)
{
    const float* pred   = (const float*)d_in[0];  // (16,1,2048,2048) f32
    const int*   pos    = (const int*)  d_in[1];  // (16,5000,2) i32
    const float* runoff = (const float*)d_in[2];  // (16,5000) f32
    float* out = (float*)d_out;

    // Zero the 4-byte accumulator (graph-capturable async memset node).
    cudaMemsetAsync(out, 0, sizeof(float), 0);

    station_loss_kernel<<<NBLK, THREADS>>>(pred, pos, runoff, out);
}